// round 10
// baseline (speedup 1.0000x reference)
#include <cuda_runtime.h>
#include <cuda_bf16.h>
#include <cstdint>
#include <math.h>

#define BATCH 4
#define SEQ 2048
#define DMODEL 1024
#define HEADS 16
#define DEPTH 64
#define NELEM (BATCH * SEQ * DMODEL)
#define WELEM (DMODEL * DMODEL)

// ---- persistent bf16 hi/lo scratch ----
__device__ __nv_bfloat16 g_qh[NELEM], g_ql[NELEM];
__device__ __nv_bfloat16 g_kh[NELEM], g_kl[NELEM];
__device__ __nv_bfloat16 g_vh[NELEM], g_vl[NELEM];
__device__ __nv_bfloat16 g_wqh[WELEM], g_wql[WELEM];
__device__ __nv_bfloat16 g_wkh[WELEM], g_wkl[WELEM];
__device__ __nv_bfloat16 g_wvh[WELEM], g_wvl[WELEM];
__device__ __nv_bfloat16 g_wdh[WELEM], g_wdl[WELEM];
__device__ __nv_bfloat16 g_Qh[NELEM], g_Ql[NELEM];   // [bh][s][64]
__device__ __nv_bfloat16 g_Kh[NELEM], g_Kl[NELEM];
__device__ __nv_bfloat16 g_Vh[NELEM], g_Vl[NELEM];
__device__ __nv_bfloat16 g_Oh[NELEM], g_Ol[NELEM];   // flat [m][1024]

// ===========================================================================
// helpers
// ===========================================================================
__device__ __forceinline__ uint32_t smem_u32(const void* p) {
    uint32_t a;
    asm("{ .reg .u64 t; cvta.to.shared.u64 t, %1; cvt.u32.u64 %0, t; }"
        : "=r"(a) : "l"(p));
    return a;
}

__device__ __forceinline__ void mma_bf16(float* c, const uint32_t* a,
                                         uint32_t b0, uint32_t b1) {
    asm volatile(
        "mma.sync.aligned.m16n8k16.row.col.f32.bf16.bf16.f32 "
        "{%0,%1,%2,%3},{%4,%5,%6,%7},{%8,%9},{%0,%1,%2,%3};"
        : "+f"(c[0]), "+f"(c[1]), "+f"(c[2]), "+f"(c[3])
        : "r"(a[0]), "r"(a[1]), "r"(a[2]), "r"(a[3]), "r"(b0), "r"(b1));
}

__device__ __forceinline__ void ldsm_x4(uint32_t* r, uint32_t addr) {
    asm volatile("ldmatrix.sync.aligned.m8n8.x4.shared.b16 {%0,%1,%2,%3}, [%4];"
        : "=r"(r[0]), "=r"(r[1]), "=r"(r[2]), "=r"(r[3]) : "r"(addr));
}
__device__ __forceinline__ void ldsm_x4_t(uint32_t* r, uint32_t addr) {
    asm volatile("ldmatrix.sync.aligned.m8n8.x4.trans.shared.b16 {%0,%1,%2,%3}, [%4];"
        : "=r"(r[0]), "=r"(r[1]), "=r"(r[2]), "=r"(r[3]) : "r"(addr));
}

#define CP_ASYNC16(saddr, gptr) \
    asm volatile("cp.async.cg.shared.global [%0], [%1], 16;" \
                 :: "r"(saddr), "l"(gptr))
#define CP_COMMIT() asm volatile("cp.async.commit_group;")
#define CP_WAIT(n)  asm volatile("cp.async.wait_group %0;" :: "n"(n))

__device__ __forceinline__ float fast_ex2(float x) {
    float r;
    asm("ex2.approx.f32 %0, %1;" : "=f"(r) : "f"(x));
    return r;
}

__device__ __forceinline__ uint32_t pack2_hi(float x, float y) {
    __nv_bfloat162 t;
    t.x = __float2bfloat16(x);
    t.y = __float2bfloat16(y);
    return *(uint32_t*)&t;
}
__device__ __forceinline__ uint32_t pack2_lo(float x, float y, uint32_t hp) {
    __nv_bfloat162 h = *(__nv_bfloat162*)&hp;
    __nv_bfloat162 t;
    t.x = __float2bfloat16(x - __bfloat162float(h.x));
    t.y = __float2bfloat16(y - __bfloat162float(h.y));
    return *(uint32_t*)&t;
}

// ===========================================================================
// split: fp32 -> bf16 hi/lo planes
// ===========================================================================
__global__ __launch_bounds__(256) void split_pair(
    const float* __restrict__ in, __nv_bfloat16* __restrict__ hi,
    __nv_bfloat16* __restrict__ lo, int n4)
{
    const int i = blockIdx.x * 256 + threadIdx.x;
    if (i < n4) {
        float4 x = ((const float4*)in)[i];
        uint32_t h0 = pack2_hi(x.x, x.y);
        uint32_t h1 = pack2_hi(x.z, x.w);
        uint32_t l0 = pack2_lo(x.x, x.y, h0);
        uint32_t l1 = pack2_lo(x.z, x.w, h1);
        uint2 hv; hv.x = h0; hv.y = h1;
        uint2 lv; lv.x = l0; lv.y = l1;
        ((uint2*)hi)[i] = hv;
        ((uint2*)lo)[i] = lv;
    }
}

// ===========================================================================
// bf16 split GEMM with cp.async double buffering.
// ===========================================================================
#define BM 128
#define BN 128
#define BK 32
#define NCHUNK (DMODEL / BK)
#define SKS 40
#define PLANE (128 * SKS)
#define GEMM_SMEM (2 * 4 * PLANE * 2)   // 81920 B

__global__ __launch_bounds__(256, 1)
void gemm_bs(const __nv_bfloat16* __restrict__ Ahg, const __nv_bfloat16* __restrict__ Alg,
             const __nv_bfloat16* __restrict__ Whg, const __nv_bfloat16* __restrict__ Wlg,
             const float* __restrict__ bias,
             float* __restrict__ Cf,
             __nv_bfloat16* __restrict__ Chi, __nv_bfloat16* __restrict__ Clo,
             int outMode)
{
    extern __shared__ __nv_bfloat16 sm[];
    const int tid = threadIdx.x;
    const int lane = tid & 31;
    const int wid = tid >> 5;
    const int wm = (wid >> 2) * 64;
    const int wn = (wid & 3) * 32;
    const int m0 = blockIdx.y * BM;
    const int n0 = blockIdx.x * BN;
    const uint32_t sbase = smem_u32(sm);

    const int mt = lane >> 3, rw = lane & 7;
    const int aro = (mt & 1) * 8 + rw;
    const int aco = (mt >> 1) * 8;
    const int bro = (mt >> 1) * 8 + rw;
    const int bco = (mt & 1) * 8;
    const int crow = tid >> 2;
    const int cc8 = (tid & 3) * 8;

    float acc[4][4][4];
    #pragma unroll
    for (int mi = 0; mi < 4; mi++)
        #pragma unroll
        for (int ni = 0; ni < 4; ni++)
            #pragma unroll
            for (int t = 0; t < 4; t++) acc[mi][ni][t] = 0.0f;

    // async fill of one chunk into stage (byte base saddr)
    auto fill = [&](uint32_t saddr, int k0) {
        #pragma unroll
        for (int i = 0; i < 2; i++) {
            const int row = crow + i * 64;
            const size_t ga = (size_t)(m0 + row) * DMODEL + k0 + cc8;
            const size_t gb = (size_t)(n0 + row) * DMODEL + k0 + cc8;
            const uint32_t so = (uint32_t)(row * SKS + cc8) * 2;
            CP_ASYNC16(saddr + 0 * PLANE * 2 + so, Ahg + ga);
            CP_ASYNC16(saddr + 1 * PLANE * 2 + so, Alg + ga);
            CP_ASYNC16(saddr + 2 * PLANE * 2 + so, Whg + gb);
            CP_ASYNC16(saddr + 3 * PLANE * 2 + so, Wlg + gb);
        }
    };

    fill(sbase, 0);
    CP_COMMIT();

    for (int c = 0; c < NCHUNK; c++) {
        const int s = c & 1;
        const uint32_t cur = sbase + (uint32_t)s * 4 * PLANE * 2;
        if (c + 1 < NCHUNK) {
            fill(sbase + (uint32_t)(s ^ 1) * 4 * PLANE * 2, (c + 1) * BK);
            CP_COMMIT();
            CP_WAIT(1);
        } else {
            CP_WAIT(0);
        }
        __syncthreads();

        #pragma unroll
        for (int ks = 0; ks < BK; ks += 16) {
            uint32_t ah[4][4], al[4][4], bh[2][4], bl[2][4];
            #pragma unroll
            for (int mi = 0; mi < 4; mi++) {
                const uint32_t off =
                    (uint32_t)((wm + mi * 16 + aro) * SKS + ks + aco) * 2;
                ldsm_x4(ah[mi], cur + 0 * PLANE * 2 + off);
                ldsm_x4(al[mi], cur + 1 * PLANE * 2 + off);
            }
            #pragma unroll
            for (int nip = 0; nip < 2; nip++) {
                const uint32_t off =
                    (uint32_t)((wn + nip * 16 + bro) * SKS + ks + bco) * 2;
                ldsm_x4(bh[nip], cur + 2 * PLANE * 2 + off);
                ldsm_x4(bl[nip], cur + 3 * PLANE * 2 + off);
            }
            #pragma unroll
            for (int mi = 0; mi < 4; mi++)
                #pragma unroll
                for (int ni = 0; ni < 4; ni++) {
                    const int nip = ni >> 1, o = (ni & 1) * 2;
                    mma_bf16(acc[mi][ni], ah[mi], bh[nip][o], bh[nip][o + 1]);
                    mma_bf16(acc[mi][ni], ah[mi], bl[nip][o], bl[nip][o + 1]);
                    mma_bf16(acc[mi][ni], al[mi], bh[nip][o], bh[nip][o + 1]);
                }
        }
        __syncthreads();
    }

    #pragma unroll
    for (int mi = 0; mi < 4; mi++) {
        const int r = m0 + wm + mi * 16 + (lane >> 2);
        #pragma unroll
        for (int ni = 0; ni < 4; ni++) {
            const int n = n0 + wn + ni * 8 + (lane & 3) * 2;
            const float b0 = bias[n], b1 = bias[n + 1];
            const float v00 = acc[mi][ni][0] + b0, v01 = acc[mi][ni][1] + b1;
            const float v10 = acc[mi][ni][2] + b0, v11 = acc[mi][ni][3] + b1;
            if (outMode == 0) {
                float2 t0; t0.x = v00; t0.y = v01;
                float2 t1; t1.x = v10; t1.y = v11;
                *(float2*)&Cf[(size_t)r * DMODEL + n] = t0;
                *(float2*)&Cf[(size_t)(r + 8) * DMODEL + n] = t1;
            } else {
                const int bb = r >> 11, ss = r & (SEQ - 1);
                const int hh = n >> 6, dd = n & 63;
                const size_t o0 =
                    ((size_t)(bb * HEADS + hh) * SEQ + ss) * DEPTH + dd;
                const size_t o1 = o0 + 8 * DEPTH;
                const uint32_t h0 = pack2_hi(v00, v01);
                const uint32_t l0 = pack2_lo(v00, v01, h0);
                const uint32_t h1 = pack2_hi(v10, v11);
                const uint32_t l1 = pack2_lo(v10, v11, h1);
                *(uint32_t*)&Chi[o0] = h0; *(uint32_t*)&Clo[o0] = l0;
                *(uint32_t*)&Chi[o1] = h1; *(uint32_t*)&Clo[o1] = l1;
            }
        }
    }
}

// ===========================================================================
// Flash attention v3: 128-row q tiles, 256 threads (8 warps), cp.async
// double-buffered K/V stages, causal with per-warp skip of fully-masked tiles.
// ===========================================================================
#define SLD 72
#define APLANE (64 * SLD)
#define ASTAGEB (4 * APLANE * 2)          // 36864 B per stage
#define ATTN_SMEM (2 * ASTAGEB)           // 73728 B

__global__ __launch_bounds__(256, 1) void attn_mma3()
{
    extern __shared__ __nv_bfloat16 sms[];
    const int tid = threadIdx.x;
    const int lane = tid & 31;
    const int wid = tid >> 5;              // 0..7
    const int g = lane >> 2;
    const int qq = lane & 3;
    const int qt = (int)gridDim.x - 1 - (int)blockIdx.x;   // heavy first
    const int bh = blockIdx.y;
    const int qbase = qt * 128;
    const int wrow = qbase + wid * 16;     // warp min q-row (absolute)
    const size_t bhoff = (size_t)bh * SEQ * DEPTH;
    const uint32_t sbase = smem_u32(sms);

    const int mt = lane >> 3, rw = lane & 7;
    const int k_ro = (mt >> 1) * 8 + rw;
    const int k_co = (mt & 1) * 8;
    const int v_ro = (mt & 1) * 8 + rw;
    const int v_co = (mt >> 1) * 8;

    // Q frags from global hi/lo planes
    uint32_t qh[4][4], ql[4][4];
    {
        const size_t r0 = bhoff + (size_t)(wrow + g) * DEPTH;
        const size_t r1 = r0 + 8 * DEPTH;
        #pragma unroll
        for (int kd = 0; kd < 4; kd++) {
            const int c = kd * 16 + qq * 2;
            qh[kd][0] = *(const uint32_t*)&g_Qh[r0 + c];
            qh[kd][1] = *(const uint32_t*)&g_Qh[r1 + c];
            qh[kd][2] = *(const uint32_t*)&g_Qh[r0 + c + 8];
            qh[kd][3] = *(const uint32_t*)&g_Qh[r1 + c + 8];
            ql[kd][0] = *(const uint32_t*)&g_Ql[r0 + c];
            ql[kd][1] = *(const uint32_t*)&g_Ql[r1 + c];
            ql[kd][2] = *(const uint32_t*)&g_Ql[r0 + c + 8];
            ql[kd][3] = *(const uint32_t*)&g_Ql[r1 + c + 8];
        }
    }

    float m0 = -INFINITY, m1 = -INFINITY, l0 = 0.0f, l1 = 0.0f;
    float oac[8][4];
    #pragma unroll
    for (int nj = 0; nj < 8; nj++)
        #pragma unroll
        for (int t = 0; t < 4; t++) oac[nj][t] = 0.0f;

    const float fscale = 0.125f * 1.4426950408889634f;
    const int nkt = 2 * qt + 2;

    // async fill of one kv tile into stage
    auto fill = [&](uint32_t saddr, int kt) {
        #pragma unroll
        for (int i = 0; i < 8; i++) {
            const int plane = i >> 1;
            const int w = tid + (i & 1) * 256;
            const int row = w >> 3, c8 = (w & 7) * 8;
            const size_t gsrc = bhoff + (size_t)(kt * 64 + row) * DEPTH + c8;
            const uint32_t so =
                saddr + (uint32_t)(plane * APLANE + row * SLD + c8) * 2;
            const __nv_bfloat16* src =
                (plane == 0) ? g_Kh : (plane == 1) ? g_Kl
              : (plane == 2) ? g_Vh : g_Vl;
            CP_ASYNC16(so, src + gsrc);
        }
    };

    fill(sbase, 0);
    CP_COMMIT();

    for (int kt = 0; kt < nkt; kt++) {
        const int s = kt & 1;
        const uint32_t cur = sbase + (uint32_t)s * ASTAGEB;
        if (kt + 1 < nkt) {
            fill(sbase + (uint32_t)(s ^ 1) * ASTAGEB, kt + 1);
            CP_COMMIT();
            CP_WAIT(1);
        } else {
            CP_WAIT(0);
        }
        __syncthreads();

        const bool active = (kt * 64) <= (wrow + 15);
        if (active) {
            // S = Q K^T
            float sa[8][4];
            #pragma unroll
            for (int ni = 0; ni < 8; ni++)
                #pragma unroll
                for (int t = 0; t < 4; t++) sa[ni][t] = 0.0f;

            #pragma unroll
            for (int kd = 0; kd < 4; kd++) {
                #pragma unroll
                for (int nip = 0; nip < 4; nip++) {
                    const uint32_t off =
                        (uint32_t)((nip * 16 + k_ro) * SLD + kd * 16 + k_co) * 2;
                    uint32_t kh4[4], kl4[4];
                    ldsm_x4(kh4, cur + off);
                    ldsm_x4(kl4, cur + APLANE * 2 + off);
                    const int n0i = nip * 2;
                    mma_bf16(sa[n0i], qh[kd], kh4[0], kh4[1]);
                    mma_bf16(sa[n0i], qh[kd], kl4[0], kl4[1]);
                    mma_bf16(sa[n0i], ql[kd], kh4[0], kh4[1]);
                    mma_bf16(sa[n0i + 1], qh[kd], kh4[2], kh4[3]);
                    mma_bf16(sa[n0i + 1], qh[kd], kl4[2], kl4[3]);
                    mma_bf16(sa[n0i + 1], ql[kd], kh4[2], kh4[3]);
                }
            }

            // causal mask (absolute indices) only near diagonal
            if (kt * 64 + 63 > wrow) {
                const int rl0 = wrow + g;
                const int rl1 = rl0 + 8;
                #pragma unroll
                for (int ni = 0; ni < 8; ni++) {
                    const int cl = kt * 64 + ni * 8 + qq * 2;
                    if (cl > rl0)     sa[ni][0] = -1e30f;
                    if (cl + 1 > rl0) sa[ni][1] = -1e30f;
                    if (cl > rl1)     sa[ni][2] = -1e30f;
                    if (cl + 1 > rl1) sa[ni][3] = -1e30f;
                }
            }

            // online softmax
            float mx0 = -1e30f, mx1 = -1e30f;
            #pragma unroll
            for (int ni = 0; ni < 8; ni++) {
                mx0 = fmaxf(mx0, fmaxf(sa[ni][0], sa[ni][1]));
                mx1 = fmaxf(mx1, fmaxf(sa[ni][2], sa[ni][3]));
            }
            mx0 = fmaxf(mx0, __shfl_xor_sync(0xffffffffu, mx0, 1));
            mx0 = fmaxf(mx0, __shfl_xor_sync(0xffffffffu, mx0, 2));
            mx1 = fmaxf(mx1, __shfl_xor_sync(0xffffffffu, mx1, 1));
            mx1 = fmaxf(mx1, __shfl_xor_sync(0xffffffffu, mx1, 2));
            const float nm0 = fmaxf(m0, mx0);
            const float nm1 = fmaxf(m1, mx1);
            const float al0 = fast_ex2((m0 - nm0) * fscale);
            const float al1 = fast_ex2((m1 - nm1) * fscale);
            m0 = nm0; m1 = nm1;

            float sum0 = 0.0f, sum1 = 0.0f;
            uint32_t pah[4][4], pal[4][4];
            #pragma unroll
            for (int ni = 0; ni < 8; ni++) {
                const float p0 = fast_ex2((sa[ni][0] - m0) * fscale);
                const float p1 = fast_ex2((sa[ni][1] - m0) * fscale);
                const float p2 = fast_ex2((sa[ni][2] - m1) * fscale);
                const float p3 = fast_ex2((sa[ni][3] - m1) * fscale);
                sum0 += p0 + p1;
                sum1 += p2 + p3;
                const int ks = ni >> 1;
                const int hl = (ni & 1) << 1;
                pah[ks][hl + 0] = pack2_hi(p0, p1);
                pal[ks][hl + 0] = pack2_lo(p0, p1, pah[ks][hl + 0]);
                pah[ks][hl + 1] = pack2_hi(p2, p3);
                pal[ks][hl + 1] = pack2_lo(p2, p3, pah[ks][hl + 1]);
            }
            l0 = l0 * al0 + sum0;
            l1 = l1 * al1 + sum1;

            #pragma unroll
            for (int nj = 0; nj < 8; nj++) {
                oac[nj][0] *= al0; oac[nj][1] *= al0;
                oac[nj][2] *= al1; oac[nj][3] *= al1;
            }

            // O += P V
            #pragma unroll
            for (int ks = 0; ks < 4; ks++) {
                #pragma unroll
                for (int njp = 0; njp < 4; njp++) {
                    const uint32_t off =
                        (uint32_t)((ks * 16 + v_ro) * SLD + njp * 16 + v_co) * 2;
                    uint32_t vh4[4], vl4[4];
                    ldsm_x4_t(vh4, cur + 2 * APLANE * 2 + off);
                    ldsm_x4_t(vl4, cur + 3 * APLANE * 2 + off);
                    const int nj0 = njp * 2;
                    mma_bf16(oac[nj0], pah[ks], vh4[0], vh4[1]);
                    mma_bf16(oac[nj0], pah[ks], vl4[0], vl4[1]);
                    mma_bf16(oac[nj0], pal[ks], vh4[0], vh4[1]);
                    mma_bf16(oac[nj0 + 1], pah[ks], vh4[2], vh4[3]);
                    mma_bf16(oac[nj0 + 1], pah[ks], vl4[2], vl4[3]);
                    mma_bf16(oac[nj0 + 1], pal[ks], vh4[2], vh4[3]);
                }
            }
        }
        __syncthreads();
    }

    // finalize -> hi/lo planes flat [m][1024]
    l0 += __shfl_xor_sync(0xffffffffu, l0, 1);
    l0 += __shfl_xor_sync(0xffffffffu, l0, 2);
    l1 += __shfl_xor_sync(0xffffffffu, l1, 1);
    l1 += __shfl_xor_sync(0xffffffffu, l1, 2);
    const float inv0 = 1.0f / l0;
    const float inv1 = 1.0f / l1;

    const int bb = bh >> 4;
    const int hh = bh & 15;
    const size_t r0m = (size_t)(bb * SEQ + wrow + g) * DMODEL + hh * DEPTH;
    const size_t r1m = r0m + 8 * DMODEL;
    #pragma unroll
    for (int nj = 0; nj < 8; nj++) {
        const int d = nj * 8 + qq * 2;
        const float v0 = oac[nj][0] * inv0, v1 = oac[nj][1] * inv0;
        const float w0 = oac[nj][2] * inv1, w1 = oac[nj][3] * inv1;
        const uint32_t hp0 = pack2_hi(v0, v1);
        const uint32_t lp0 = pack2_lo(v0, v1, hp0);
        const uint32_t hp1 = pack2_hi(w0, w1);
        const uint32_t lp1 = pack2_lo(w0, w1, hp1);
        *(uint32_t*)&g_Oh[r0m + d] = hp0;
        *(uint32_t*)&g_Ol[r0m + d] = lp0;
        *(uint32_t*)&g_Oh[r1m + d] = hp1;
        *(uint32_t*)&g_Ol[r1m + d] = lp1;
    }
}

// ===========================================================================
extern "C" void kernel_launch(void* const* d_in, const int* in_sizes, int n_in,
                              void* d_out, int out_size)
{
    const float* q    = (const float*)d_in[0];
    const float* k    = (const float*)d_in[1];
    const float* v    = (const float*)d_in[2];
    const float* wq_w = (const float*)d_in[3];
    const float* wq_b = (const float*)d_in[4];
    const float* wk_w = (const float*)d_in[5];
    const float* wk_b = (const float*)d_in[6];
    const float* wv_w = (const float*)d_in[7];
    const float* wv_b = (const float*)d_in[8];
    const float* dw   = (const float*)d_in[9];
    const float* db   = (const float*)d_in[10];
    float* out = (float*)d_out;

    __nv_bfloat16 *qh, *ql, *kh, *kl, *vh, *vl;
    __nv_bfloat16 *wqh, *wql, *wkh, *wkl, *wvh, *wvl, *wdh, *wdl;
    __nv_bfloat16 *Qh, *Ql, *Kh, *Kl, *Vh, *Vl, *Oh, *Ol;
    cudaGetSymbolAddress((void**)&qh, g_qh);   cudaGetSymbolAddress((void**)&ql, g_ql);
    cudaGetSymbolAddress((void**)&kh, g_kh);   cudaGetSymbolAddress((void**)&kl, g_kl);
    cudaGetSymbolAddress((void**)&vh, g_vh);   cudaGetSymbolAddress((void**)&vl, g_vl);
    cudaGetSymbolAddress((void**)&wqh, g_wqh); cudaGetSymbolAddress((void**)&wql, g_wql);
    cudaGetSymbolAddress((void**)&wkh, g_wkh); cudaGetSymbolAddress((void**)&wkl, g_wkl);
    cudaGetSymbolAddress((void**)&wvh, g_wvh); cudaGetSymbolAddress((void**)&wvl, g_wvl);
    cudaGetSymbolAddress((void**)&wdh, g_wdh); cudaGetSymbolAddress((void**)&wdl, g_wdl);
    cudaGetSymbolAddress((void**)&Qh, g_Qh);   cudaGetSymbolAddress((void**)&Ql, g_Ql);
    cudaGetSymbolAddress((void**)&Kh, g_Kh);   cudaGetSymbolAddress((void**)&Kl, g_Kl);
    cudaGetSymbolAddress((void**)&Vh, g_Vh);   cudaGetSymbolAddress((void**)&Vl, g_Vl);
    cudaGetSymbolAddress((void**)&Oh, g_Oh);   cudaGetSymbolAddress((void**)&Ol, g_Ol);

    cudaFuncSetAttribute(gemm_bs,
                         cudaFuncAttributeMaxDynamicSharedMemorySize, GEMM_SMEM);
    cudaFuncSetAttribute(attn_mma3,
                         cudaFuncAttributeMaxDynamicSharedMemorySize, ATTN_SMEM);

    const int n4i = NELEM / 4, n4w = WELEM / 4;
    split_pair<<<n4i / 256, 256>>>(q, qh, ql, n4i);
    split_pair<<<n4i / 256, 256>>>(k, kh, kl, n4i);
    split_pair<<<n4i / 256, 256>>>(v, vh, vl, n4i);
    split_pair<<<n4w / 256, 256>>>(wq_w, wqh, wql, n4w);
    split_pair<<<n4w / 256, 256>>>(wk_w, wkh, wkl, n4w);
    split_pair<<<n4w / 256, 256>>>(wv_w, wvh, wvl, n4w);
    split_pair<<<n4w / 256, 256>>>(dw, wdh, wdl, n4w);

    dim3 gemmGrid(DMODEL / 128, (BATCH * SEQ) / 128);
    gemm_bs<<<gemmGrid, 256, GEMM_SMEM>>>(qh, ql, wqh, wql, wq_b,
                                          nullptr, Qh, Ql, 1);
    gemm_bs<<<gemmGrid, 256, GEMM_SMEM>>>(kh, kl, wkh, wkl, wk_b,
                                          nullptr, Kh, Kl, 1);
    gemm_bs<<<gemmGrid, 256, GEMM_SMEM>>>(vh, vl, wvh, wvl, wv_b,
                                          nullptr, Vh, Vl, 1);

    dim3 attnGrid(SEQ / 128, BATCH * HEADS);           // (16, 64)
    attn_mma3<<<attnGrid, 256, ATTN_SMEM>>>();

    gemm_bs<<<gemmGrid, 256, GEMM_SMEM>>>(Oh, Ol, wdh, wdl, db,
                                          out, nullptr, nullptr, 0);
}

// round 12
// speedup vs baseline: 1.0921x; 1.0921x over previous
#include <cuda_runtime.h>
#include <cuda_bf16.h>
#include <cstdint>
#include <math.h>

#define BATCH 4
#define SEQ 2048
#define DMODEL 1024
#define HEADS 16
#define DEPTH 64
#define NELEM (BATCH * SEQ * DMODEL)
#define WELEM (DMODEL * DMODEL)

// ---- persistent bf16 hi/lo scratch ----
__device__ __nv_bfloat16 g_qh[NELEM], g_ql[NELEM];
__device__ __nv_bfloat16 g_kh[NELEM], g_kl[NELEM];
__device__ __nv_bfloat16 g_vh[NELEM], g_vl[NELEM];
__device__ __nv_bfloat16 g_wqh[WELEM], g_wql[WELEM];
__device__ __nv_bfloat16 g_wkh[WELEM], g_wkl[WELEM];
__device__ __nv_bfloat16 g_wvh[WELEM], g_wvl[WELEM];
__device__ __nv_bfloat16 g_wdh[WELEM], g_wdl[WELEM];
__device__ __nv_bfloat16 g_Qh[NELEM], g_Ql[NELEM];   // [bh][s][64]
__device__ __nv_bfloat16 g_Kh[NELEM], g_Kl[NELEM];
__device__ __nv_bfloat16 g_Vh[NELEM], g_Vl[NELEM];
__device__ __nv_bfloat16 g_Oh[NELEM], g_Ol[NELEM];   // flat [m][1024]

// ===========================================================================
// helpers
// ===========================================================================
__device__ __forceinline__ uint32_t smem_u32(const void* p) {
    uint32_t a;
    asm("{ .reg .u64 t; cvta.to.shared.u64 t, %1; cvt.u32.u64 %0, t; }"
        : "=r"(a) : "l"(p));
    return a;
}

__device__ __forceinline__ void mma_bf16(float* c, const uint32_t* a,
                                         uint32_t b0, uint32_t b1) {
    asm volatile(
        "mma.sync.aligned.m16n8k16.row.col.f32.bf16.bf16.f32 "
        "{%0,%1,%2,%3},{%4,%5,%6,%7},{%8,%9},{%0,%1,%2,%3};"
        : "+f"(c[0]), "+f"(c[1]), "+f"(c[2]), "+f"(c[3])
        : "r"(a[0]), "r"(a[1]), "r"(a[2]), "r"(a[3]), "r"(b0), "r"(b1));
}

__device__ __forceinline__ void ldsm_x4(uint32_t* r, uint32_t addr) {
    asm volatile("ldmatrix.sync.aligned.m8n8.x4.shared.b16 {%0,%1,%2,%3}, [%4];"
        : "=r"(r[0]), "=r"(r[1]), "=r"(r[2]), "=r"(r[3]) : "r"(addr));
}
__device__ __forceinline__ void ldsm_x4_t(uint32_t* r, uint32_t addr) {
    asm volatile("ldmatrix.sync.aligned.m8n8.x4.trans.shared.b16 {%0,%1,%2,%3}, [%4];"
        : "=r"(r[0]), "=r"(r[1]), "=r"(r[2]), "=r"(r[3]) : "r"(addr));
}

#define CP_ASYNC16(saddr, gptr) \
    asm volatile("cp.async.cg.shared.global [%0], [%1], 16;" \
                 :: "r"(saddr), "l"(gptr))
#define CP_COMMIT() asm volatile("cp.async.commit_group;")
#define CP_WAIT(n)  asm volatile("cp.async.wait_group %0;" :: "n"(n))

__device__ __forceinline__ float fast_ex2(float x) {
    float r;
    asm("ex2.approx.f32 %0, %1;" : "=f"(r) : "f"(x));
    return r;
}

__device__ __forceinline__ uint32_t pack2_hi(float x, float y) {
    __nv_bfloat162 t;
    t.x = __float2bfloat16(x);
    t.y = __float2bfloat16(y);
    return *(uint32_t*)&t;
}
__device__ __forceinline__ uint32_t pack2_lo(float x, float y, uint32_t hp) {
    __nv_bfloat162 h = *(__nv_bfloat162*)&hp;
    __nv_bfloat162 t;
    t.x = __float2bfloat16(x - __bfloat162float(h.x));
    t.y = __float2bfloat16(y - __bfloat162float(h.y));
    return *(uint32_t*)&t;
}

// ===========================================================================
// split: fp32 -> bf16 hi/lo planes
// ===========================================================================
__global__ __launch_bounds__(256) void split_pair(
    const float* __restrict__ in, __nv_bfloat16* __restrict__ hi,
    __nv_bfloat16* __restrict__ lo, int n4)
{
    const int i = blockIdx.x * 256 + threadIdx.x;
    if (i < n4) {
        float4 x = ((const float4*)in)[i];
        uint32_t h0 = pack2_hi(x.x, x.y);
        uint32_t h1 = pack2_hi(x.z, x.w);
        uint32_t l0 = pack2_lo(x.x, x.y, h0);
        uint32_t l1 = pack2_lo(x.z, x.w, h1);
        uint2 hv; hv.x = h0; hv.y = h1;
        uint2 lv; lv.x = l0; lv.y = l1;
        ((uint2*)hi)[i] = hv;
        ((uint2*)lo)[i] = lv;
    }
}

// ===========================================================================
// bf16 split GEMM, cp.async double buffering, 2 CTAs/SM for latency hiding.
// ===========================================================================
#define BM 128
#define BN 128
#define BK 32
#define NCHUNK (DMODEL / BK)
#define SKS 40
#define PLANE (128 * SKS)
#define GEMM_SMEM (2 * 4 * PLANE * 2)   // 81920 B  (2 stages)

__global__ __launch_bounds__(256, 2)
void gemm_bs(const __nv_bfloat16* __restrict__ Ahg, const __nv_bfloat16* __restrict__ Alg,
             const __nv_bfloat16* __restrict__ Whg, const __nv_bfloat16* __restrict__ Wlg,
             const float* __restrict__ bias,
             float* __restrict__ Cf,
             __nv_bfloat16* __restrict__ Chi, __nv_bfloat16* __restrict__ Clo,
             int outMode)
{
    extern __shared__ __nv_bfloat16 sm[];
    const int tid = threadIdx.x;
    const int lane = tid & 31;
    const int wid = tid >> 5;
    const int wm = (wid >> 2) * 64;
    const int wn = (wid & 3) * 32;
    const int m0 = blockIdx.y * BM;
    const int n0 = blockIdx.x * BN;
    const uint32_t sbase = smem_u32(sm);

    const int mt = lane >> 3, rw = lane & 7;
    const int aro = (mt & 1) * 8 + rw;
    const int aco = (mt >> 1) * 8;
    const int bro = (mt >> 1) * 8 + rw;
    const int bco = (mt & 1) * 8;
    const int crow = tid >> 2;
    const int cc8 = (tid & 3) * 8;

    float acc[4][4][4];
    #pragma unroll
    for (int mi = 0; mi < 4; mi++)
        #pragma unroll
        for (int ni = 0; ni < 4; ni++)
            #pragma unroll
            for (int t = 0; t < 4; t++) acc[mi][ni][t] = 0.0f;

    auto fill = [&](uint32_t saddr, int k0) {
        #pragma unroll
        for (int i = 0; i < 2; i++) {
            const int row = crow + i * 64;
            const size_t ga = (size_t)(m0 + row) * DMODEL + k0 + cc8;
            const size_t gb = (size_t)(n0 + row) * DMODEL + k0 + cc8;
            const uint32_t so = (uint32_t)(row * SKS + cc8) * 2;
            CP_ASYNC16(saddr + 0 * PLANE * 2 + so, Ahg + ga);
            CP_ASYNC16(saddr + 1 * PLANE * 2 + so, Alg + ga);
            CP_ASYNC16(saddr + 2 * PLANE * 2 + so, Whg + gb);
            CP_ASYNC16(saddr + 3 * PLANE * 2 + so, Wlg + gb);
        }
    };

    fill(sbase, 0);
    CP_COMMIT();

    for (int c = 0; c < NCHUNK; c++) {
        const int s = c & 1;
        const uint32_t cur = sbase + (uint32_t)s * 4 * PLANE * 2;
        if (c + 1 < NCHUNK) {
            fill(sbase + (uint32_t)(s ^ 1) * 4 * PLANE * 2, (c + 1) * BK);
            CP_COMMIT();
            CP_WAIT(1);
        } else {
            CP_WAIT(0);
        }
        __syncthreads();

        #pragma unroll
        for (int ks = 0; ks < BK; ks += 16) {
            uint32_t ah[4][4], al[4][4], bh[2][4], bl[2][4];
            #pragma unroll
            for (int mi = 0; mi < 4; mi++) {
                const uint32_t off =
                    (uint32_t)((wm + mi * 16 + aro) * SKS + ks + aco) * 2;
                ldsm_x4(ah[mi], cur + 0 * PLANE * 2 + off);
                ldsm_x4(al[mi], cur + 1 * PLANE * 2 + off);
            }
            #pragma unroll
            for (int nip = 0; nip < 2; nip++) {
                const uint32_t off =
                    (uint32_t)((wn + nip * 16 + bro) * SKS + ks + bco) * 2;
                ldsm_x4(bh[nip], cur + 2 * PLANE * 2 + off);
                ldsm_x4(bl[nip], cur + 3 * PLANE * 2 + off);
            }
            #pragma unroll
            for (int mi = 0; mi < 4; mi++)
                #pragma unroll
                for (int ni = 0; ni < 4; ni++) {
                    const int nip = ni >> 1, o = (ni & 1) * 2;
                    mma_bf16(acc[mi][ni], ah[mi], bh[nip][o], bh[nip][o + 1]);
                    mma_bf16(acc[mi][ni], ah[mi], bl[nip][o], bl[nip][o + 1]);
                    mma_bf16(acc[mi][ni], al[mi], bh[nip][o], bh[nip][o + 1]);
                }
        }
        __syncthreads();
    }

    #pragma unroll
    for (int mi = 0; mi < 4; mi++) {
        const int r = m0 + wm + mi * 16 + (lane >> 2);
        #pragma unroll
        for (int ni = 0; ni < 4; ni++) {
            const int n = n0 + wn + ni * 8 + (lane & 3) * 2;
            const float b0 = bias[n], b1 = bias[n + 1];
            const float v00 = acc[mi][ni][0] + b0, v01 = acc[mi][ni][1] + b1;
            const float v10 = acc[mi][ni][2] + b0, v11 = acc[mi][ni][3] + b1;
            if (outMode == 0) {
                float2 t0; t0.x = v00; t0.y = v01;
                float2 t1; t1.x = v10; t1.y = v11;
                *(float2*)&Cf[(size_t)r * DMODEL + n] = t0;
                *(float2*)&Cf[(size_t)(r + 8) * DMODEL + n] = t1;
            } else {
                const int bb = r >> 11, ss = r & (SEQ - 1);
                const int hh = n >> 6, dd = n & 63;
                const size_t o0 =
                    ((size_t)(bb * HEADS + hh) * SEQ + ss) * DEPTH + dd;
                const size_t o1 = o0 + 8 * DEPTH;
                const uint32_t h0 = pack2_hi(v00, v01);
                const uint32_t l0 = pack2_lo(v00, v01, h0);
                const uint32_t h1 = pack2_hi(v10, v11);
                const uint32_t l1 = pack2_lo(v10, v11, h1);
                *(uint32_t*)&Chi[o0] = h0; *(uint32_t*)&Clo[o0] = l0;
                *(uint32_t*)&Chi[o1] = h1; *(uint32_t*)&Clo[o1] = l1;
            }
        }
    }
}

// ===========================================================================
// Flash attention (R9 structure: 64-row q tiles, 128 threads), fill via
// cp.async. K frags ldmatrix, V frags ldmatrix.trans, qt reversed.
// ===========================================================================
#define SLD 72
#define APLANE (64 * SLD)
#define ATTN_SMEM (4 * APLANE * 2)   // 36864 B

__global__ __launch_bounds__(128) void attn_mma2()
{
    extern __shared__ __nv_bfloat16 sms[];
    const int tid = threadIdx.x;
    const int lane = tid & 31;
    const int wid = tid >> 5;
    const int g = lane >> 2;
    const int qq = lane & 3;
    const int qt = (int)gridDim.x - 1 - (int)blockIdx.x;
    const int bh = blockIdx.y;
    const int qbase = qt * 64;
    const size_t bhoff = (size_t)bh * SEQ * DEPTH;
    const uint32_t sK = smem_u32(sms);
    const uint32_t PBYTES = APLANE * 2;

    const int mt = lane >> 3, rw = lane & 7;
    const int k_ro = (mt >> 1) * 8 + rw;
    const int k_co = (mt & 1) * 8;
    const int v_ro = (mt & 1) * 8 + rw;
    const int v_co = (mt >> 1) * 8;

    uint32_t qh[4][4], ql[4][4];
    {
        const size_t r0 = bhoff + (size_t)(qbase + wid * 16 + g) * DEPTH;
        const size_t r1 = r0 + 8 * DEPTH;
        #pragma unroll
        for (int kd = 0; kd < 4; kd++) {
            const int c = kd * 16 + qq * 2;
            qh[kd][0] = *(const uint32_t*)&g_Qh[r0 + c];
            qh[kd][1] = *(const uint32_t*)&g_Qh[r1 + c];
            qh[kd][2] = *(const uint32_t*)&g_Qh[r0 + c + 8];
            qh[kd][3] = *(const uint32_t*)&g_Qh[r1 + c + 8];
            ql[kd][0] = *(const uint32_t*)&g_Ql[r0 + c];
            ql[kd][1] = *(const uint32_t*)&g_Ql[r1 + c];
            ql[kd][2] = *(const uint32_t*)&g_Ql[r0 + c + 8];
            ql[kd][3] = *(const uint32_t*)&g_Ql[r1 + c + 8];
        }
    }

    float m0 = -INFINITY, m1 = -INFINITY, l0 = 0.0f, l1 = 0.0f;
    float oac[8][4];
    #pragma unroll
    for (int nj = 0; nj < 8; nj++)
        #pragma unroll
        for (int t = 0; t < 4; t++) oac[nj][t] = 0.0f;

    const float fscale = 0.125f * 1.4426950408889634f;

    for (int kt = 0; kt <= qt; kt++) {
        __syncthreads();
        // K/V tile fill via cp.async (16 ops/thread)
        #pragma unroll
        for (int i = 0; i < 4; i++) {
            const int u = tid + i * 128;
            const int row = u >> 3, c8 = (u & 7) * 8;
            const size_t gsrc = bhoff + (size_t)(kt * 64 + row) * DEPTH + c8;
            const uint32_t so = (uint32_t)(row * SLD + c8) * 2;
            CP_ASYNC16(sK + 0 * PBYTES + so, g_Kh + gsrc);
            CP_ASYNC16(sK + 1 * PBYTES + so, g_Kl + gsrc);
            CP_ASYNC16(sK + 2 * PBYTES + so, g_Vh + gsrc);
            CP_ASYNC16(sK + 3 * PBYTES + so, g_Vl + gsrc);
        }
        CP_COMMIT();
        CP_WAIT(0);
        __syncthreads();

        // S = Q K^T
        float sa[8][4];
        #pragma unroll
        for (int ni = 0; ni < 8; ni++)
            #pragma unroll
            for (int t = 0; t < 4; t++) sa[ni][t] = 0.0f;

        #pragma unroll
        for (int kd = 0; kd < 4; kd++) {
            #pragma unroll
            for (int nip = 0; nip < 4; nip++) {
                const uint32_t off =
                    (uint32_t)((nip * 16 + k_ro) * SLD + kd * 16 + k_co) * 2;
                uint32_t kh4[4], kl4[4];
                ldsm_x4(kh4, sK + off);
                ldsm_x4(kl4, sK + PBYTES + off);
                const int n0i = nip * 2;
                mma_bf16(sa[n0i], qh[kd], kh4[0], kh4[1]);
                mma_bf16(sa[n0i], qh[kd], kl4[0], kl4[1]);
                mma_bf16(sa[n0i], ql[kd], kh4[0], kh4[1]);
                mma_bf16(sa[n0i + 1], qh[kd], kh4[2], kh4[3]);
                mma_bf16(sa[n0i + 1], qh[kd], kl4[2], kl4[3]);
                mma_bf16(sa[n0i + 1], ql[kd], kh4[2], kh4[3]);
            }
        }

        if (kt == qt) {
            const int rl0 = wid * 16 + g;
            const int rl1 = rl0 + 8;
            #pragma unroll
            for (int ni = 0; ni < 8; ni++) {
                const int cl = ni * 8 + qq * 2;
                if (cl > rl0)     sa[ni][0] = -1e30f;
                if (cl + 1 > rl0) sa[ni][1] = -1e30f;
                if (cl > rl1)     sa[ni][2] = -1e30f;
                if (cl + 1 > rl1) sa[ni][3] = -1e30f;
            }
        }

        float mx0 = -1e30f, mx1 = -1e30f;
        #pragma unroll
        for (int ni = 0; ni < 8; ni++) {
            mx0 = fmaxf(mx0, fmaxf(sa[ni][0], sa[ni][1]));
            mx1 = fmaxf(mx1, fmaxf(sa[ni][2], sa[ni][3]));
        }
        mx0 = fmaxf(mx0, __shfl_xor_sync(0xffffffffu, mx0, 1));
        mx0 = fmaxf(mx0, __shfl_xor_sync(0xffffffffu, mx0, 2));
        mx1 = fmaxf(mx1, __shfl_xor_sync(0xffffffffu, mx1, 1));
        mx1 = fmaxf(mx1, __shfl_xor_sync(0xffffffffu, mx1, 2));
        const float nm0 = fmaxf(m0, mx0);
        const float nm1 = fmaxf(m1, mx1);
        const float al0 = fast_ex2((m0 - nm0) * fscale);
        const float al1 = fast_ex2((m1 - nm1) * fscale);
        m0 = nm0; m1 = nm1;

        float sum0 = 0.0f, sum1 = 0.0f;
        uint32_t pah[4][4], pal[4][4];
        #pragma unroll
        for (int ni = 0; ni < 8; ni++) {
            const float p0 = fast_ex2((sa[ni][0] - m0) * fscale);
            const float p1 = fast_ex2((sa[ni][1] - m0) * fscale);
            const float p2 = fast_ex2((sa[ni][2] - m1) * fscale);
            const float p3 = fast_ex2((sa[ni][3] - m1) * fscale);
            sum0 += p0 + p1;
            sum1 += p2 + p3;
            const int ks = ni >> 1;
            const int hl = (ni & 1) << 1;
            pah[ks][hl + 0] = pack2_hi(p0, p1);
            pal[ks][hl + 0] = pack2_lo(p0, p1, pah[ks][hl + 0]);
            pah[ks][hl + 1] = pack2_hi(p2, p3);
            pal[ks][hl + 1] = pack2_lo(p2, p3, pah[ks][hl + 1]);
        }
        l0 = l0 * al0 + sum0;
        l1 = l1 * al1 + sum1;

        #pragma unroll
        for (int nj = 0; nj < 8; nj++) {
            oac[nj][0] *= al0; oac[nj][1] *= al0;
            oac[nj][2] *= al1; oac[nj][3] *= al1;
        }

        #pragma unroll
        for (int ks = 0; ks < 4; ks++) {
            #pragma unroll
            for (int njp = 0; njp < 4; njp++) {
                const uint32_t off =
                    (uint32_t)((ks * 16 + v_ro) * SLD + njp * 16 + v_co) * 2;
                uint32_t vh4[4], vl4[4];
                ldsm_x4_t(vh4, sK + 2 * PBYTES + off);
                ldsm_x4_t(vl4, sK + 3 * PBYTES + off);
                const int nj0 = njp * 2;
                mma_bf16(oac[nj0], pah[ks], vh4[0], vh4[1]);
                mma_bf16(oac[nj0], pah[ks], vl4[0], vl4[1]);
                mma_bf16(oac[nj0], pal[ks], vh4[0], vh4[1]);
                mma_bf16(oac[nj0 + 1], pah[ks], vh4[2], vh4[3]);
                mma_bf16(oac[nj0 + 1], pah[ks], vl4[2], vl4[3]);
                mma_bf16(oac[nj0 + 1], pal[ks], vh4[2], vh4[3]);
            }
        }
    }

    // finalize -> hi/lo planes flat [m][1024]
    l0 += __shfl_xor_sync(0xffffffffu, l0, 1);
    l0 += __shfl_xor_sync(0xffffffffu, l0, 2);
    l1 += __shfl_xor_sync(0xffffffffu, l1, 1);
    l1 += __shfl_xor_sync(0xffffffffu, l1, 2);
    const float inv0 = 1.0f / l0;
    const float inv1 = 1.0f / l1;

    const int bb = bh >> 4;
    const int hh = bh & 15;
    const size_t r0m =
        (size_t)(bb * SEQ + qbase + wid * 16 + g) * DMODEL + hh * DEPTH;
    const size_t r1m = r0m + 8 * DMODEL;
    #pragma unroll
    for (int nj = 0; nj < 8; nj++) {
        const int d = nj * 8 + qq * 2;
        const float v0 = oac[nj][0] * inv0, v1 = oac[nj][1] * inv0;
        const float w0 = oac[nj][2] * inv1, w1 = oac[nj][3] * inv1;
        const uint32_t hp0 = pack2_hi(v0, v1);
        const uint32_t lp0 = pack2_lo(v0, v1, hp0);
        const uint32_t hp1 = pack2_hi(w0, w1);
        const uint32_t lp1 = pack2_lo(w0, w1, hp1);
        *(uint32_t*)&g_Oh[r0m + d] = hp0;
        *(uint32_t*)&g_Ol[r0m + d] = lp0;
        *(uint32_t*)&g_Oh[r1m + d] = hp1;
        *(uint32_t*)&g_Ol[r1m + d] = lp1;
    }
}

// ===========================================================================
extern "C" void kernel_launch(void* const* d_in, const int* in_sizes, int n_in,
                              void* d_out, int out_size)
{
    const float* q    = (const float*)d_in[0];
    const float* k    = (const float*)d_in[1];
    const float* v    = (const float*)d_in[2];
    const float* wq_w = (const float*)d_in[3];
    const float* wq_b = (const float*)d_in[4];
    const float* wk_w = (const float*)d_in[5];
    const float* wk_b = (const float*)d_in[6];
    const float* wv_w = (const float*)d_in[7];
    const float* wv_b = (const float*)d_in[8];
    const float* dw   = (const float*)d_in[9];
    const float* db   = (const float*)d_in[10];
    float* out = (float*)d_out;

    __nv_bfloat16 *qh, *ql, *kh, *kl, *vh, *vl;
    __nv_bfloat16 *wqh, *wql, *wkh, *wkl, *wvh, *wvl, *wdh, *wdl;
    __nv_bfloat16 *Qh, *Ql, *Kh, *Kl, *Vh, *Vl, *Oh, *Ol;
    cudaGetSymbolAddress((void**)&qh, g_qh);   cudaGetSymbolAddress((void**)&ql, g_ql);
    cudaGetSymbolAddress((void**)&kh, g_kh);   cudaGetSymbolAddress((void**)&kl, g_kl);
    cudaGetSymbolAddress((void**)&vh, g_vh);   cudaGetSymbolAddress((void**)&vl, g_vl);
    cudaGetSymbolAddress((void**)&wqh, g_wqh); cudaGetSymbolAddress((void**)&wql, g_wql);
    cudaGetSymbolAddress((void**)&wkh, g_wkh); cudaGetSymbolAddress((void**)&wkl, g_wkl);
    cudaGetSymbolAddress((void**)&wvh, g_wvh); cudaGetSymbolAddress((void**)&wvl, g_wvl);
    cudaGetSymbolAddress((void**)&wdh, g_wdh); cudaGetSymbolAddress((void**)&wdl, g_wdl);
    cudaGetSymbolAddress((void**)&Qh, g_Qh);   cudaGetSymbolAddress((void**)&Ql, g_Ql);
    cudaGetSymbolAddress((void**)&Kh, g_Kh);   cudaGetSymbolAddress((void**)&Kl, g_Kl);
    cudaGetSymbolAddress((void**)&Vh, g_Vh);   cudaGetSymbolAddress((void**)&Vl, g_Vl);
    cudaGetSymbolAddress((void**)&Oh, g_Oh);   cudaGetSymbolAddress((void**)&Ol, g_Ol);

    cudaFuncSetAttribute(gemm_bs,
                         cudaFuncAttributeMaxDynamicSharedMemorySize, GEMM_SMEM);
    cudaFuncSetAttribute(attn_mma2,
                         cudaFuncAttributeMaxDynamicSharedMemorySize, ATTN_SMEM);

    const int n4i = NELEM / 4, n4w = WELEM / 4;
    split_pair<<<n4i / 256, 256>>>(q, qh, ql, n4i);
    split_pair<<<n4i / 256, 256>>>(k, kh, kl, n4i);
    split_pair<<<n4i / 256, 256>>>(v, vh, vl, n4i);
    split_pair<<<n4w / 256, 256>>>(wq_w, wqh, wql, n4w);
    split_pair<<<n4w / 256, 256>>>(wk_w, wkh, wkl, n4w);
    split_pair<<<n4w / 256, 256>>>(wv_w, wvh, wvl, n4w);
    split_pair<<<n4w / 256, 256>>>(dw, wdh, wdl, n4w);

    dim3 gemmGrid(DMODEL / 128, (BATCH * SEQ) / 128);
    gemm_bs<<<gemmGrid, 256, GEMM_SMEM>>>(qh, ql, wqh, wql, wq_b,
                                          nullptr, Qh, Ql, 1);
    gemm_bs<<<gemmGrid, 256, GEMM_SMEM>>>(kh, kl, wkh, wkl, wk_b,
                                          nullptr, Kh, Kl, 1);
    gemm_bs<<<gemmGrid, 256, GEMM_SMEM>>>(vh, vl, wvh, wvl, wv_b,
                                          nullptr, Vh, Vl, 1);

    dim3 attnGrid(SEQ / 64, BATCH * HEADS);            // (32, 64)
    attn_mma2<<<attnGrid, 128, ATTN_SMEM>>>();

    gemm_bs<<<gemmGrid, 256, GEMM_SMEM>>>(Oh, Ol, wdh, wdl, db,
                                          out, nullptr, nullptr, 0);
}